// round 3
// baseline (speedup 1.0000x reference)
#include <cuda_runtime.h>
#include <cuda_bf16.h>
#include <cstdint>

#define DIMV 64
#define TM   80            // rows per CTA (5 warps x 16)
#define WARPS_PER_CTA 5

// x^T in bf16: B operand [n][k] (n = DIM index, k = row index), stride N
__device__ __nv_bfloat16 g_xT[64 * 10240];

// ---------------- helpers ----------------
__device__ __forceinline__ uint32_t cvt_bf16x2(float lo, float hi) {
    uint32_t r;
    asm("cvt.rn.bf16x2.f32 %0, %1, %2;" : "=r"(r) : "f"(hi), "f"(lo));
    return r;
}

__device__ __forceinline__ void mma16816(float c[4], const uint32_t a[4],
                                         uint32_t b0, uint32_t b1) {
    asm volatile(
        "mma.sync.aligned.m16n8k16.row.col.f32.bf16.bf16.f32 "
        "{%0,%1,%2,%3}, {%4,%5,%6,%7}, {%8,%9}, {%0,%1,%2,%3};"
        : "+f"(c[0]), "+f"(c[1]), "+f"(c[2]), "+f"(c[3])
        : "r"(a[0]), "r"(a[1]), "r"(a[2]), "r"(a[3]), "r"(b0), "r"(b1));
}

// ---------------- kernel 1: x [N,64] fp32 -> xT [64,N] bf16 ----------------
__global__ void __launch_bounds__(256) xpose_kernel(const float* __restrict__ x, int N) {
    __shared__ float t[64][65];
    int k0 = blockIdx.x * 64;
    for (int i = threadIdx.x; i < 64 * 64; i += 256) {
        int r = i >> 6, d = i & 63;
        int k = k0 + r;
        t[r][d] = (k < N) ? x[(size_t)k * DIMV + d] : 0.0f;
    }
    __syncthreads();
    for (int i = threadIdx.x; i < 64 * 64; i += 256) {
        int d = i >> 6, r = i & 63;
        int k = k0 + r;
        if (k < N) g_xT[(size_t)d * N + k] = __float2bfloat16(t[r][d]);
    }
}

// ---------------- kernel 2: fused GEMM + epilogue (register HMMA) ----------------
// Each warp: rows [rowbase, rowbase+16), all 64 output cols, full K.
// N must be a multiple of 16; grid*TM == N exactly (10000 = 125*80).
__global__ void __launch_bounds__(WARPS_PER_CTA * 32, 1)
gemm_kernel(const float* __restrict__ A, const float* __restrict__ x,
            float* __restrict__ out, int N) {
    int tid  = threadIdx.x;
    int w    = tid >> 5;
    int lane = tid & 31;
    int g = lane >> 2;        // 0..7
    int t = lane & 3;         // 0..3

    int rowbase = blockIdx.x * TM + w * 16;
    int r0 = rowbase + g;     // always < N (exact tiling)
    int r1 = r0 + 8;

    const float* pA0 = A + (size_t)r0 * N + t * 2;
    const float* pA1 = A + (size_t)r1 * N + t * 2;

    // B tile pointers: xT[n][k], n = j*8+g, starting at k element t*2
    const __nv_bfloat16* pB[8];
#pragma unroll
    for (int j = 0; j < 8; j++)
        pB[j] = g_xT + (size_t)(j * 8 + g) * N + t * 2;

    float c[8][4];
#pragma unroll
    for (int j = 0; j < 8; j++)
#pragma unroll
        for (int q = 0; q < 4; q++) c[j][q] = 0.0f;

    int nk = N >> 4;          // K-steps of 16
#pragma unroll 4
    for (int ks = 0; ks < nk; ks++) {
        int k0 = ks << 4;

        // A fragment: 4x float2 (rows g,g+8 ; k cols t*2 and t*2+8)
        float2 a01 = *(const float2*)(pA0 + k0);
        float2 a23 = *(const float2*)(pA1 + k0);
        float2 a45 = *(const float2*)(pA0 + k0 + 8);
        float2 a67 = *(const float2*)(pA1 + k0 + 8);

        // B fragments: 8 n-tiles x 2 regs (k = t*2 and t*2+8), bf16 pairs
        uint32_t b[8][2];
#pragma unroll
        for (int j = 0; j < 8; j++) {
            b[j][0] = *(const uint32_t*)(pB[j] + k0);
            b[j][1] = *(const uint32_t*)(pB[j] + k0 + 8);
        }

        uint32_t ar[4];
        ar[0] = cvt_bf16x2(a01.x, a01.y);
        ar[1] = cvt_bf16x2(a23.x, a23.y);
        ar[2] = cvt_bf16x2(a45.x, a45.y);
        ar[3] = cvt_bf16x2(a67.x, a67.y);

#pragma unroll
        for (int j = 0; j < 8; j++)
            mma16816(c[j], ar, b[j][0], b[j][1]);
    }

    // ---- epilogue ----
    // Lane owns Ax[r0][col], Ax[r0][col+1] in c[j][0..1] and Ax[r1][...] in c[j][2..3],
    // col = j*8 + t*2. Dot with x, reduce across the 4 t-lanes (same g => same rows).
    float2 x0[8], x1[8];
    float s0 = 0.0f, s1 = 0.0f;
#pragma unroll
    for (int j = 0; j < 8; j++) {
        int col = j * 8 + t * 2;
        x0[j] = *(const float2*)(x + (size_t)r0 * DIMV + col);
        x1[j] = *(const float2*)(x + (size_t)r1 * DIMV + col);
        s0 += x0[j].x * c[j][0] + x0[j].y * c[j][1];
        s1 += x1[j].x * c[j][2] + x1[j].y * c[j][3];
    }
    s0 += __shfl_xor_sync(0xFFFFFFFFu, s0, 1);
    s0 += __shfl_xor_sync(0xFFFFFFFFu, s0, 2);
    s1 += __shfl_xor_sync(0xFFFFFFFFu, s1, 1);
    s1 += __shfl_xor_sync(0xFFFFFFFFu, s1, 2);

    float i0 = 0.01f * s0;
    float i1 = 0.01f * s1;

#pragma unroll
    for (int j = 0; j < 8; j++) {
        int col = j * 8 + t * 2;
        float2 o0, o1;
        o0.x = 1.0f - 0.1f * x0[j].x - i0;
        o0.y = 1.0f - 0.1f * x0[j].y - i0;
        o1.x = 1.0f - 0.1f * x1[j].x - i1;
        o1.y = 1.0f - 0.1f * x1[j].y - i1;
        *(float2*)(out + (size_t)r0 * DIMV + col) = o0;
        *(float2*)(out + (size_t)r1 * DIMV + col) = o1;
    }
}

// ---------------- launch ----------------
extern "C" void kernel_launch(void* const* d_in, const int* in_sizes, int n_in,
                              void* d_out, int out_size) {
    const float* x = (const float*)d_in[1];
    const float* A = (const float*)d_in[2];
    float* out = (float*)d_out;
    int N = in_sizes[1] / DIMV;   // 10000

    xpose_kernel<<<(N + 63) / 64, 256>>>(x, N);

    int grid = (N + TM - 1) / TM; // 125, exact: 125*80 == 10000
    gemm_kernel<<<grid, WARPS_PER_CTA * 32>>>(A, x, out, N);
}

// round 4
// speedup vs baseline: 1.9489x; 1.9489x over previous
#include <cuda_runtime.h>
#include <cuda_bf16.h>
#include <cstdint>

#define DIMV 64
#define WPC  6    // warps per CTA (split-K ways)

// B packed in mma-fragment order: Bp[(ks*8 + j)*32 + lane] = {b0, b1}
// b0 = bf16x2{ x[k0+2t][n], x[k0+2t+1][n] }, b1 = same at k0+8, n = j*8+g
__device__ uint2 g_Bp[640 * 8 * 32];

// ---------------- helpers ----------------
__device__ __forceinline__ uint32_t cvt_bf16x2(float lo, float hi) {
    uint32_t r;
    asm("cvt.rn.bf16x2.f32 %0, %1, %2;" : "=r"(r) : "f"(hi), "f"(lo));
    return r;
}

__device__ __forceinline__ void mma16816(float c[4], const uint32_t a[4],
                                         uint32_t b0, uint32_t b1) {
    asm volatile(
        "mma.sync.aligned.m16n8k16.row.col.f32.bf16.bf16.f32 "
        "{%0,%1,%2,%3}, {%4,%5,%6,%7}, {%8,%9}, {%0,%1,%2,%3};"
        : "+f"(c[0]), "+f"(c[1]), "+f"(c[2]), "+f"(c[3])
        : "r"(a[0]), "r"(a[1]), "r"(a[2]), "r"(a[3]), "r"(b0), "r"(b1));
}

// ---------------- kernel 1: pack x -> Bp (fragment-ordered bf16) -------------
// grid = nk (625), block = 256 (8 j-tiles x 32 lanes)
__global__ void __launch_bounds__(256) pack_kernel(const float* __restrict__ x, int N) {
    __shared__ float xs[16][64];
    int ks = blockIdx.x;
    int k0 = ks * 16;
    for (int i = threadIdx.x; i < 16 * 64; i += 256) {
        int r = i >> 6, c = i & 63;
        xs[r][c] = x[(size_t)(k0 + r) * DIMV + c];
    }
    __syncthreads();
    int j = threadIdx.x >> 5, lane = threadIdx.x & 31;
    int g = lane >> 2, t = lane & 3;
    int n = j * 8 + g;
    uint32_t lo = cvt_bf16x2(xs[2 * t][n],     xs[2 * t + 1][n]);
    uint32_t hi = cvt_bf16x2(xs[8 + 2 * t][n], xs[8 + 2 * t + 1][n]);
    g_Bp[(size_t)(ks * 8 + j) * 32 + lane] = make_uint2(lo, hi);
}

// ---------------- kernel 2: fused GEMM + epilogue ----------------
// One CTA = one 16-row tile; 6 warps split K (strided K-steps); smem reduce.
__global__ void __launch_bounds__(WPC * 32, 2)
gemm_kernel(const float* __restrict__ A, const float* __restrict__ x,
            float* __restrict__ out, int N) {
    __shared__ float wred[WPC][16];
    __shared__ float wfin[16];

    int tid = threadIdx.x, w = tid >> 5, lane = tid & 31;
    int g = lane >> 2, t = lane & 3;
    int row0 = blockIdx.x * 16;
    int r0 = row0 + g, r1 = r0 + 8;

    const float* pA0 = A + (size_t)r0 * N + t * 2;
    const float* pA1 = A + (size_t)r1 * N + t * 2;

    float c[8][4];
#pragma unroll
    for (int j = 0; j < 8; j++)
#pragma unroll
        for (int q = 0; q < 4; q++) c[j][q] = 0.0f;

    int nk = N >> 4;  // 625 K-steps of 16
#pragma unroll 4
    for (int ks = w; ks < nk; ks += WPC) {
        int k0 = ks << 4;

        float2 a01 = *(const float2*)(pA0 + k0);
        float2 a23 = *(const float2*)(pA1 + k0);
        float2 a45 = *(const float2*)(pA0 + k0 + 8);
        float2 a67 = *(const float2*)(pA1 + k0 + 8);

        const uint2* bp = g_Bp + (size_t)ks * 256 + lane;
        uint2 bb[8];
#pragma unroll
        for (int j = 0; j < 8; j++) bb[j] = bp[(size_t)j * 32];

        uint32_t ar[4];
        ar[0] = cvt_bf16x2(a01.x, a01.y);
        ar[1] = cvt_bf16x2(a23.x, a23.y);
        ar[2] = cvt_bf16x2(a45.x, a45.y);
        ar[3] = cvt_bf16x2(a67.x, a67.y);

#pragma unroll
        for (int j = 0; j < 8; j++)
            mma16816(c[j], ar, bb[j].x, bb[j].y);
    }

    // per-warp partial dot of x . (Ax)_partial over owned columns
    float s0 = 0.0f, s1 = 0.0f;
#pragma unroll
    for (int j = 0; j < 8; j++) {
        int col = j * 8 + t * 2;
        float2 x0 = *(const float2*)(x + (size_t)r0 * DIMV + col);
        float2 x1 = *(const float2*)(x + (size_t)r1 * DIMV + col);
        s0 += x0.x * c[j][0] + x0.y * c[j][1];
        s1 += x1.x * c[j][2] + x1.y * c[j][3];
    }
    s0 += __shfl_xor_sync(0xFFFFFFFFu, s0, 1);
    s0 += __shfl_xor_sync(0xFFFFFFFFu, s0, 2);
    s1 += __shfl_xor_sync(0xFFFFFFFFu, s1, 1);
    s1 += __shfl_xor_sync(0xFFFFFFFFu, s1, 2);

    if (t == 0) { wred[w][g] = s0; wred[w][g + 8] = s1; }
    __syncthreads();

    if (tid < 16) {
        float acc = 0.0f;
#pragma unroll
        for (int q = 0; q < WPC; q++) acc += wred[q][tid];
        wfin[tid] = 0.01f * acc;
    }
    __syncthreads();

    // write out: 16 rows x 64 cols, coalesced float4
    for (int i = tid; i < 256; i += WPC * 32) {
        int r = i >> 4, cq = i & 15;
        const float* xr = x + (size_t)(row0 + r) * DIMV + cq * 4;
        float4 xv = *(const float4*)xr;
        float inter = wfin[r];
        float4 o;
        o.x = 1.0f - 0.1f * xv.x - inter;
        o.y = 1.0f - 0.1f * xv.y - inter;
        o.z = 1.0f - 0.1f * xv.z - inter;
        o.w = 1.0f - 0.1f * xv.w - inter;
        *(float4*)(out + (size_t)(row0 + r) * DIMV + cq * 4) = o;
    }
}

// ---------------- launch ----------------
extern "C" void kernel_launch(void* const* d_in, const int* in_sizes, int n_in,
                              void* d_out, int out_size) {
    const float* x = (const float*)d_in[1];
    const float* A = (const float*)d_in[2];
    float* out = (float*)d_out;
    int N = in_sizes[1] / DIMV;   // 10000
    int nk = N >> 4;              // 625

    pack_kernel<<<nk, 256>>>(x, N);
    gemm_kernel<<<N / 16, WPC * 32>>>(A, x, out, N);
}